// round 6
// baseline (speedup 1.0000x reference)
#include <cuda_runtime.h>

// Shapes (fixed by setup_inputs): D=128, H=8, N_e=50000, N_r=2000, E=800000.
#define D 128
#define H 8
#define MAXN 65536
#define MAXR 4096
#define MAXE 1048576

// ---------------- device scratch (no allocations allowed) ----------------
__device__ __align__(16) float g_eh[MAXN * H];        // x_e @ Wh^T
__device__ __align__(16) float g_et[MAXN * H];        // x_e @ Wt^T
__device__ __align__(16) float g_er[MAXR * H];        // x_r @ Wr^T
__device__ __align__(16) float g_dn[2][MAXN * H];     // denominators -> inverted in place
__device__ int   g_cnt [2 * MAXN];                    // edge count per (node, side)
__device__ int   g_base[2 * MAXN];                    // exclusive prefix (slot base)
__device__ int   g_cur [2 * MAXN];                    // fill cursors (re-init every launch)
__device__ int   g_bsum[256];                         // per-block sums for the scan
__device__ int   g_boff[256];                         // scanned block offsets
__device__ int   g_pr[2 * MAXE];                      // payload: relation id per slot
__device__ __align__(16) float g_pex[(size_t)2 * MAXE * 8]; // payload: 8 exp values per slot
__device__ int   g_is64;

static __device__ __forceinline__ float lrelu(float s) {
    return fmaxf(s, 0.01f * s);
}

// ---------------- index dtype detection ----------------
// int64 little-endian with values < 2^31: every odd 32-bit word is 0.
__global__ void k_detect(const unsigned* __restrict__ ei) {
    if (blockIdx.x == 0 && threadIdx.x == 0) {
        int ok = 1;
        for (int i = 0; i < 128; i++)
            if (ei[2 * i + 1] != 0u) { ok = 0; break; }
        g_is64 = ok;
    }
}

static __device__ __forceinline__ void load_edge(const void* ei, const void* rl, int e, int E,
                                                 long long& h, long long& t, long long& r) {
    if (g_is64) {
        h = ((const long long*)ei)[e];
        t = ((const long long*)ei)[(long long)E + e];
        r = ((const long long*)rl)[e];
    } else {
        h = ((const int*)ei)[e];
        t = ((const int*)ei)[(long long)E + e];
        r = ((const int*)rl)[e];
    }
}

// ---------------- degree histogram (indices only) ----------------
__global__ void k_count(const void* __restrict__ ei, int E, int N_e) {
    int e = blockIdx.x * blockDim.x + threadIdx.x;
    if (e >= E) return;
    long long h, t;
    if (g_is64) {
        h = ((const long long*)ei)[e];
        t = ((const long long*)ei)[(long long)E + e];
    } else {
        h = ((const int*)ei)[e];
        t = ((const int*)ei)[(long long)E + e];
    }
    atomicAdd(&g_cnt[(int)h], 1);
    atomicAdd(&g_cnt[N_e + (int)t], 1);
}

// ---------------- fused projections (N_e + N_r blocks) ----------------
__global__ void k_proj(const float* __restrict__ Xe, const float* __restrict__ Xr,
                       const float* __restrict__ Wh, const float* __restrict__ Wt,
                       const float* __restrict__ Wr, int N_e, int N_r) {
    __shared__ float sx[D];
    int b = blockIdx.x;
    int warp = threadIdx.x >> 5, lane = threadIdx.x & 31;
    if (b < N_e) {
        sx[threadIdx.x] = Xe[(size_t)b * D + threadIdx.x];
        __syncthreads();
#pragma unroll
        for (int i = 0; i < 4; i++) {
            int o = warp * 4 + i;                 // 0..15: 8 Wh heads then 8 Wt heads
            const float* W = ((o < H) ? Wh : Wt) + (size_t)(o & (H - 1)) * D;
            float s = sx[lane] * W[lane] + sx[lane + 32] * W[lane + 32]
                    + sx[lane + 64] * W[lane + 64] + sx[lane + 96] * W[lane + 96];
#pragma unroll
            for (int off = 16; off; off >>= 1) s += __shfl_xor_sync(0xffffffffu, s, off);
            if (lane == 0) ((o < H) ? g_eh : g_et)[(size_t)b * H + (o & (H - 1))] = s;
        }
    } else {
        int n = b - N_e;
        if (n >= N_r) return;
        sx[threadIdx.x] = Xr[(size_t)n * D + threadIdx.x];
        __syncthreads();
#pragma unroll
        for (int i = 0; i < 2; i++) {
            int o = warp * 2 + i;
            const float* W = Wr + (size_t)o * D;
            float s = sx[lane] * W[lane] + sx[lane + 32] * W[lane + 32]
                    + sx[lane + 64] * W[lane + 64] + sx[lane + 96] * W[lane + 96];
#pragma unroll
            for (int off = 16; off; off >>= 1) s += __shfl_xor_sync(0xffffffffu, s, off);
            if (lane == 0) g_er[(size_t)n * H + o] = s;
        }
    }
}

// ---------------- init ----------------
__global__ void k_zero(int NH, int NN) {
    int i = blockIdx.x * blockDim.x + threadIdx.x;
    if (i < NH) { g_dn[0][i] = 0.0f; g_dn[1][i] = 0.0f; }
    if (i < NN) g_cnt[i] = 0;
}

// ---------------- 3-kernel exclusive scan over g_cnt[0..NN) ----------------
__global__ void k_scan1(int NN) {
    __shared__ int sm[1024];
    int i = blockIdx.x * 1024 + threadIdx.x;
    sm[threadIdx.x] = (i < NN) ? g_cnt[i] : 0;
    __syncthreads();
    for (int off = 512; off; off >>= 1) {
        if (threadIdx.x < off) sm[threadIdx.x] += sm[threadIdx.x + off];
        __syncthreads();
    }
    if (threadIdx.x == 0) g_bsum[blockIdx.x] = sm[0];
}
__global__ void k_scan2(int nb) {
    if (blockIdx.x == 0 && threadIdx.x == 0) {
        int acc = 0;
#pragma unroll 1
        for (int b = 0; b < nb; b++) { g_boff[b] = acc; acc += g_bsum[b]; }
    }
}
__global__ void k_scan3(int NN) {
    __shared__ int sm[1024];
    int i = blockIdx.x * 1024 + threadIdx.x;
    int v = (i < NN) ? g_cnt[i] : 0;
    sm[threadIdx.x] = v;
    __syncthreads();
    for (int off = 1; off < 1024; off <<= 1) {   // Hillis-Steele inclusive
        int tv = (threadIdx.x >= off) ? sm[threadIdx.x - off] : 0;
        __syncthreads();
        sm[threadIdx.x] += tv;
        __syncthreads();
    }
    if (i < NN) {
        int excl = sm[threadIdx.x] - v + g_boff[blockIdx.x];
        g_base[i] = excl;
        g_cur[i]  = excl;    // fill cursor, re-initialized every launch
    }
}

// ---------------- fused edge pass: exp + dn atomics + payload --------------
// One thread per edge. No max subtraction: scores are leaky_relu of ~N(0,2)
// sums, exp in [~0.9, ~5000] -> fp32-safe, identical softmax.
// Payload stores raw exp values; the per-head division is deferred to the
// gather (inv_dn loaded once per node-side there).
__global__ void k_expfill(const void* __restrict__ ei, const void* __restrict__ rl,
                          int E, int N_e) {
    int e = blockIdx.x * blockDim.x + threadIdx.x;
    if (e >= E) return;
    long long h, t, r;
    load_edge(ei, rl, e, E, h, t, r);
    float er_[H], eh_[H], et_[H], exh[H], ext[H];
    *(float4*)&er_[0] = ((const float4*)g_er)[r * 2];
    *(float4*)&er_[4] = ((const float4*)g_er)[r * 2 + 1];
    *(float4*)&eh_[0] = ((const float4*)g_eh)[h * 2];
    *(float4*)&eh_[4] = ((const float4*)g_eh)[h * 2 + 1];
    *(float4*)&et_[0] = ((const float4*)g_et)[t * 2];
    *(float4*)&et_[4] = ((const float4*)g_et)[t * 2 + 1];
#pragma unroll
    for (int k = 0; k < H; k++) {
        exh[k] = __expf(lrelu(eh_[k] + er_[k]));
        ext[k] = __expf(lrelu(et_[k] + er_[k]));
    }
    atomicAdd((float4*)&g_dn[0][h * H],     *(float4*)&exh[0]);
    atomicAdd((float4*)&g_dn[0][h * H + 4], *(float4*)&exh[4]);
    atomicAdd((float4*)&g_dn[1][t * H],     *(float4*)&ext[0]);
    atomicAdd((float4*)&g_dn[1][t * H + 4], *(float4*)&ext[4]);

    int ph = atomicAdd(&g_cur[(int)h], 1);
    g_pr[ph] = (int)r;
    ((float4*)&g_pex[(size_t)ph * 8])[0] = *(float4*)&exh[0];
    ((float4*)&g_pex[(size_t)ph * 8])[1] = *(float4*)&exh[4];

    int pt = atomicAdd(&g_cur[N_e + (int)t], 1);
    g_pr[pt] = (int)r;
    ((float4*)&g_pex[(size_t)pt * 8])[0] = *(float4*)&ext[0];
    ((float4*)&g_pex[(size_t)pt * 8])[1] = *(float4*)&ext[4];
}

// ---------------- invert denominators ----------------
__global__ void k_recip(int NH) {
    int i = blockIdx.x * blockDim.x + threadIdx.x;
    if (i < NH) {
        g_dn[0][i] = 1.0f / (g_dn[0][i] + 1e-16f);
        g_dn[1][i] = 1.0f / (g_dn[1][i] + 1e-16f);
    }
}

// ---------------- gather: one warp per (node, side), no output atomics -----
// Lane jl computes its payload element's alpha (dot with warp-uniform inv_dn);
// row addresses come from broadcast loads of g_pr (keeps LDGs off the shuffle
// chain), unrolled x4 for MLP.
__global__ void k_gather(const float* __restrict__ xr, float* __restrict__ out,
                         int N_e, int NN) {
    int gw = (int)(((long long)blockIdx.x * blockDim.x + threadIdx.x) >> 5);
    int lane = threadIdx.x & 31;
    if (gw >= NN) return;
    int side = (gw >= N_e);
    int n    = side ? gw - N_e : gw;
    int deg  = g_cnt[gw];
    int base = g_base[gw];
    float ivd[8];
    *(float4*)&ivd[0] = *(const float4*)&g_dn[side][n * H];
    *(float4*)&ivd[4] = *(const float4*)&g_dn[side][n * H + 4];
    const float4* xr4 = (const float4*)xr;
    float4 acc = make_float4(0.f, 0.f, 0.f, 0.f);

    for (int j0 = 0; j0 < deg; j0 += 32) {
        int jl = j0 + lane;
        float a = 0.f;
        if (jl < deg) {
            float4 e0 = ((const float4*)&g_pex[(size_t)(base + jl) * 8])[0];
            float4 e1 = ((const float4*)&g_pex[(size_t)(base + jl) * 8])[1];
            a = (e0.x * ivd[0] + e0.y * ivd[1] + e0.z * ivd[2] + e0.w * ivd[3]
               + e1.x * ivd[4] + e1.y * ivd[5] + e1.z * ivd[6] + e1.w * ivd[7]) * 0.125f;
        }
        int m = min(32, deg - j0);
        int k = 0;
        for (; k + 4 <= m; k += 4) {
            int r0 = g_pr[base + j0 + k];
            int r1 = g_pr[base + j0 + k + 1];
            int r2 = g_pr[base + j0 + k + 2];
            int r3 = g_pr[base + j0 + k + 3];
            float a0 = __shfl_sync(0xffffffffu, a, k);
            float a1 = __shfl_sync(0xffffffffu, a, k + 1);
            float a2 = __shfl_sync(0xffffffffu, a, k + 2);
            float a3 = __shfl_sync(0xffffffffu, a, k + 3);
            float4 v0 = xr4[(size_t)r0 * 32 + lane];
            float4 v1 = xr4[(size_t)r1 * 32 + lane];
            float4 v2 = xr4[(size_t)r2 * 32 + lane];
            float4 v3 = xr4[(size_t)r3 * 32 + lane];
            acc.x += a0 * v0.x; acc.y += a0 * v0.y; acc.z += a0 * v0.z; acc.w += a0 * v0.w;
            acc.x += a1 * v1.x; acc.y += a1 * v1.y; acc.z += a1 * v1.z; acc.w += a1 * v1.w;
            acc.x += a2 * v2.x; acc.y += a2 * v2.y; acc.z += a2 * v2.z; acc.w += a2 * v2.w;
            acc.x += a3 * v3.x; acc.y += a3 * v3.y; acc.z += a3 * v3.z; acc.w += a3 * v3.w;
        }
        for (; k < m; k++) {
            int   rk = g_pr[base + j0 + k];
            float ak = __shfl_sync(0xffffffffu, a, k);
            float4 v = xr4[(size_t)rk * 32 + lane];
            acc.x += ak * v.x; acc.y += ak * v.y; acc.z += ak * v.z; acc.w += ak * v.w;
        }
    }
    // out row = 256 floats = 64 float4: h-side cols [0,128), t-side [128,256)
    ((float4*)out)[(size_t)n * 64 + side * 32 + lane] = acc;
}

// ---------------- host ----------------
extern "C" void kernel_launch(void* const* d_in, const int* in_sizes, int n_in,
                              void* d_out, int out_size) {
    const float* x_e = (const float*)d_in[0];
    const float* x_r = (const float*)d_in[1];
    const float* Wh  = (const float*)d_in[2];
    const float* Wt  = (const float*)d_in[3];
    const float* Wr  = (const float*)d_in[4];
    const void*  ei  = d_in[5];
    const void*  rl  = d_in[6];
    float* out = (float*)d_out;

    int N_e = in_sizes[0] / D;
    int N_r = in_sizes[1] / D;
    int E   = in_sizes[6];
    int NH  = N_e * H;
    int NN  = 2 * N_e;
    int nb  = (NN + 1023) / 1024;
    int eb  = (E + 255) / 256;

    k_zero<<<(NH + 255) / 256, 256>>>(NH, NN);
    k_detect<<<1, 32>>>((const unsigned*)ei);
    k_count<<<eb, 256>>>(ei, E, N_e);
    k_proj<<<N_e + N_r, D>>>(x_e, x_r, Wh, Wt, Wr, N_e, N_r);

    k_scan1<<<nb, 1024>>>(NN);
    k_scan2<<<1, 32>>>(nb);
    k_scan3<<<nb, 1024>>>(NN);

    k_expfill<<<eb, 256>>>(ei, rl, E, N_e);
    k_recip<<<(NH + 255) / 256, 256>>>(NH);

    long long gt = (long long)NN * 32;
    k_gather<<<(int)((gt + 511) / 512), 512>>>(x_r, out, N_e, NN);
}

// round 7
// speedup vs baseline: 1.2935x; 1.2935x over previous
#include <cuda_runtime.h>

// Shapes (fixed by setup_inputs): D=128, H=8, N_e=50000, N_r=2000, E=800000.
#define D 128
#define H 8
#define MAXN 65536
#define MAXR 4096
#define MAXE 1048576

// ---------------- device scratch (no allocations allowed) ----------------
__device__ __align__(16) float g_eh[MAXN * H];        // x_e @ Wh^T
__device__ __align__(16) float g_et[MAXN * H];        // x_e @ Wt^T
__device__ __align__(16) float g_er[MAXR * H];        // x_r @ Wr^T
__device__ __align__(16) float g_dn[2][MAXN * H];     // denominators -> inverted in place
__device__ int  g_cnt [2 * MAXN];                     // edge count per (node, side)
__device__ int  g_base[2 * MAXN];                     // exclusive prefix (slot base)
__device__ int  g_cur [2 * MAXN];                     // fill cursors (re-init every launch)
__device__ int  g_bsum[256];                          // per-block sums for the scan
__device__ int  g_boff[256];                          // scanned block offsets
__device__ __align__(8) int2 g_pay[2 * MAXE];         // payload: (relation, alpha-bits)
__device__ int  g_is64;

static __device__ __forceinline__ float lrelu(float s) {
    return fmaxf(s, 0.01f * s);
}

// ---------------- index dtype detection ----------------
// int64 little-endian with values < 2^31: every odd 32-bit word is 0.
__global__ void k_detect(const unsigned* __restrict__ ei) {
    if (blockIdx.x == 0 && threadIdx.x == 0) {
        int ok = 1;
        for (int i = 0; i < 128; i++)
            if (ei[2 * i + 1] != 0u) { ok = 0; break; }
        g_is64 = ok;
    }
}

static __device__ __forceinline__ void load_edge(const void* ei, const void* rl, int e, int E,
                                                 long long& h, long long& t, long long& r) {
    if (g_is64) {
        h = ((const long long*)ei)[e];
        t = ((const long long*)ei)[(long long)E + e];
        r = ((const long long*)rl)[e];
    } else {
        h = ((const int*)ei)[e];
        t = ((const int*)ei)[(long long)E + e];
        r = ((const int*)rl)[e];
    }
}

// ---------------- projections: warp per node, shuffle-tree reduction -------
// Lane holds a float4 of the node row. 16 partials (64 FMA) from coalesced
// L1-resident W loads, then a split-and-reduce tree: all 16 outputs in
// 16 shuffles (8+4+2+1+1) instead of 16 full butterflies (80).
__global__ void k_proj(const float* __restrict__ Xe, const float* __restrict__ Xr,
                       const float* __restrict__ Wh, const float* __restrict__ Wt,
                       const float* __restrict__ Wr, int N_e, int N_r) {
    const unsigned FULL = 0xffffffffu;
    int w = (int)(((long long)blockIdx.x * blockDim.x + threadIdx.x) >> 5);
    int lane = threadIdx.x & 31;
    if (w < N_e) {
        float4 x = ((const float4*)Xe)[(size_t)w * 32 + lane];
        float p[16];
#pragma unroll
        for (int o = 0; o < 16; o++) {
            const float4* W4 = (const float4*)(((o < 8) ? Wh : Wt) + (size_t)(o & 7) * D);
            float4 wv = W4[lane];
            p[o] = x.x * wv.x + x.y * wv.y + x.z * wv.z + x.w * wv.w;
        }
        // step 16: outputs split by lane bit 4
        float q[8];
        {
            bool hi = (lane & 16) != 0;
#pragma unroll
            for (int i = 0; i < 8; i++) {
                float send = hi ? p[i] : p[i + 8];
                float recv = __shfl_xor_sync(FULL, send, 16);
                q[i] = (hi ? p[i + 8] : p[i]) + recv;
            }
        }
        float s[4];
        {
            bool hi = (lane & 8) != 0;
#pragma unroll
            for (int i = 0; i < 4; i++) {
                float send = hi ? q[i] : q[i + 4];
                float recv = __shfl_xor_sync(FULL, send, 8);
                s[i] = (hi ? q[i + 4] : q[i]) + recv;
            }
        }
        float u[2];
        {
            bool hi = (lane & 4) != 0;
#pragma unroll
            for (int i = 0; i < 2; i++) {
                float send = hi ? s[i] : s[i + 2];
                float recv = __shfl_xor_sync(FULL, send, 4);
                u[i] = (hi ? s[i + 2] : s[i]) + recv;
            }
        }
        float v;
        {
            bool hi = (lane & 2) != 0;
            float send = hi ? u[0] : u[1];
            float recv = __shfl_xor_sync(FULL, send, 2);
            v = (hi ? u[1] : u[0]) + recv;
        }
        v += __shfl_xor_sync(FULL, v, 1);
        if (!(lane & 1)) {
            int o = ((lane >> 4) & 1) * 8 + ((lane >> 3) & 1) * 4
                  + ((lane >> 2) & 1) * 2 + ((lane >> 1) & 1);
            if (o < 8) g_eh[(size_t)w * H + o] = v;
            else       g_et[(size_t)w * H + (o - 8)] = v;
        }
    } else {
        int n = w - N_e;
        if (n >= N_r) return;
        float4 x = ((const float4*)Xr)[(size_t)n * 32 + lane];
        float p[8];
#pragma unroll
        for (int o = 0; o < 8; o++) {
            const float4* W4 = (const float4*)(Wr + (size_t)o * D);
            float4 wv = W4[lane];
            p[o] = x.x * wv.x + x.y * wv.y + x.z * wv.z + x.w * wv.w;
        }
        float q[4];
        {
            bool hi = (lane & 16) != 0;
#pragma unroll
            for (int i = 0; i < 4; i++) {
                float send = hi ? p[i] : p[i + 4];
                float recv = __shfl_xor_sync(FULL, send, 16);
                q[i] = (hi ? p[i + 4] : p[i]) + recv;
            }
        }
        float s[2];
        {
            bool hi = (lane & 8) != 0;
#pragma unroll
            for (int i = 0; i < 2; i++) {
                float send = hi ? q[i] : q[i + 2];
                float recv = __shfl_xor_sync(FULL, send, 8);
                s[i] = (hi ? q[i + 2] : q[i]) + recv;
            }
        }
        float v;
        {
            bool hi = (lane & 4) != 0;
            float send = hi ? s[0] : s[1];
            float recv = __shfl_xor_sync(FULL, send, 4);
            v = (hi ? s[1] : s[0]) + recv;
        }
        v += __shfl_xor_sync(FULL, v, 2);
        v += __shfl_xor_sync(FULL, v, 1);
        if (!(lane & 3)) {
            int o = ((lane >> 4) & 1) * 4 + ((lane >> 3) & 1) * 2 + ((lane >> 2) & 1);
            g_er[(size_t)n * H + o] = v;
        }
    }
}

// ---------------- init ----------------
__global__ void k_zero(int NH, int NN) {
    int i = blockIdx.x * blockDim.x + threadIdx.x;
    if (i < NH) { g_dn[0][i] = 0.0f; g_dn[1][i] = 0.0f; }
    if (i < NN) g_cnt[i] = 0;
}

// ---------------- edge pass A: exp-sum denominators + degree histogram -----
// No max subtraction: scores are leaky_relu of ~N(0,2) sums, exp in
// [~0.9, ~5000] -> fp32-safe, mathematically identical softmax.
__global__ void k_expsum(const void* __restrict__ ei, const void* __restrict__ rl,
                         int E, int N_e) {
    int e = blockIdx.x * blockDim.x + threadIdx.x;
    if (e >= E) return;
    long long h, t, r;
    load_edge(ei, rl, e, E, h, t, r);
    float er_[H], eh_[H], et_[H], exh[H], ext[H];
    *(float4*)&er_[0] = ((const float4*)g_er)[r * 2];
    *(float4*)&er_[4] = ((const float4*)g_er)[r * 2 + 1];
    *(float4*)&eh_[0] = ((const float4*)g_eh)[h * 2];
    *(float4*)&eh_[4] = ((const float4*)g_eh)[h * 2 + 1];
    *(float4*)&et_[0] = ((const float4*)g_et)[t * 2];
    *(float4*)&et_[4] = ((const float4*)g_et)[t * 2 + 1];
#pragma unroll
    for (int k = 0; k < H; k++) {
        exh[k] = __expf(lrelu(eh_[k] + er_[k]));
        ext[k] = __expf(lrelu(et_[k] + er_[k]));
    }
    atomicAdd((float4*)&g_dn[0][h * H],     *(float4*)&exh[0]);
    atomicAdd((float4*)&g_dn[0][h * H + 4], *(float4*)&exh[4]);
    atomicAdd((float4*)&g_dn[1][t * H],     *(float4*)&ext[0]);
    atomicAdd((float4*)&g_dn[1][t * H + 4], *(float4*)&ext[4]);
    atomicAdd(&g_cnt[(int)h], 1);
    atomicAdd(&g_cnt[N_e + (int)t], 1);
}

// ---------------- invert denominators ----------------
__global__ void k_recip(int NH) {
    int i = blockIdx.x * blockDim.x + threadIdx.x;
    if (i < NH) {
        g_dn[0][i] = 1.0f / (g_dn[0][i] + 1e-16f);
        g_dn[1][i] = 1.0f / (g_dn[1][i] + 1e-16f);
    }
}

// ---------------- 3-kernel exclusive scan over g_cnt[0..NN) ----------------
__global__ void k_scan1(int NN) {
    __shared__ int sm[1024];
    int i = blockIdx.x * 1024 + threadIdx.x;
    sm[threadIdx.x] = (i < NN) ? g_cnt[i] : 0;
    __syncthreads();
    for (int off = 512; off; off >>= 1) {
        if (threadIdx.x < off) sm[threadIdx.x] += sm[threadIdx.x + off];
        __syncthreads();
    }
    if (threadIdx.x == 0) g_bsum[blockIdx.x] = sm[0];
}
__global__ void k_scan2(int nb) {
    if (blockIdx.x == 0 && threadIdx.x == 0) {
        int acc = 0;
#pragma unroll 1
        for (int b = 0; b < nb; b++) { g_boff[b] = acc; acc += g_bsum[b]; }
    }
}
__global__ void k_scan3(int NN) {
    __shared__ int sm[1024];
    int i = blockIdx.x * 1024 + threadIdx.x;
    int v = (i < NN) ? g_cnt[i] : 0;
    sm[threadIdx.x] = v;
    __syncthreads();
    for (int off = 1; off < 1024; off <<= 1) {   // Hillis-Steele inclusive
        int tv = (threadIdx.x >= off) ? sm[threadIdx.x - off] : 0;
        __syncthreads();
        sm[threadIdx.x] += tv;
        __syncthreads();
    }
    if (i < NN) {
        int excl = sm[threadIdx.x] - v + g_boff[blockIdx.x];
        g_base[i] = excl;
        g_cur[i]  = excl;    // fill cursor, re-initialized every launch
    }
}

// ---------------- edge pass B: alphas + destination-sorted payload ---------
// One thread per edge; recomputes exp (MUFU cost is negligible chip-wide)
// and writes one 8-byte (rel, alpha) payload per side.
__global__ void k_fill(const void* __restrict__ ei, const void* __restrict__ rl,
                       int E, int N_e) {
    int e = blockIdx.x * blockDim.x + threadIdx.x;
    if (e >= E) return;
    long long h, t, r;
    load_edge(ei, rl, e, E, h, t, r);
    float er_[H], eh_[H], et_[H], ivh[H], ivt[H];
    *(float4*)&er_[0] = ((const float4*)g_er)[r * 2];
    *(float4*)&er_[4] = ((const float4*)g_er)[r * 2 + 1];
    *(float4*)&eh_[0] = ((const float4*)g_eh)[h * 2];
    *(float4*)&eh_[4] = ((const float4*)g_eh)[h * 2 + 1];
    *(float4*)&et_[0] = ((const float4*)g_et)[t * 2];
    *(float4*)&et_[4] = ((const float4*)g_et)[t * 2 + 1];
    *(float4*)&ivh[0] = *(const float4*)&g_dn[0][h * H];
    *(float4*)&ivh[4] = *(const float4*)&g_dn[0][h * H + 4];
    *(float4*)&ivt[0] = *(const float4*)&g_dn[1][t * H];
    *(float4*)&ivt[4] = *(const float4*)&g_dn[1][t * H + 4];
    float ah = 0.f, at = 0.f;
#pragma unroll
    for (int k = 0; k < H; k++) {
        ah += __expf(lrelu(eh_[k] + er_[k])) * ivh[k];
        at += __expf(lrelu(et_[k] + er_[k])) * ivt[k];
    }
    ah *= 0.125f; at *= 0.125f;                       // mean over heads
    int ph = atomicAdd(&g_cur[(int)h], 1);
    g_pay[ph] = make_int2((int)r, __float_as_int(ah));
    int pt = atomicAdd(&g_cur[N_e + (int)t], 1);
    g_pay[pt] = make_int2((int)r, __float_as_int(at));
}

// ---------------- gather: one warp per (node, side), no output atomics -----
// Payloads are read with warp-uniform broadcast loads (no shuffles at all);
// x4 unroll gives MLP=4 independent 512B x_r row fetches per step.
__global__ void k_gather(const float* __restrict__ xr, float* __restrict__ out,
                         int N_e, int NN) {
    int gw = (int)(((long long)blockIdx.x * blockDim.x + threadIdx.x) >> 5);
    int lane = threadIdx.x & 31;
    if (gw >= NN) return;
    int side = (gw >= N_e);
    int n    = side ? gw - N_e : gw;
    int deg  = g_cnt[gw];
    int base = g_base[gw];
    const float4* xr4 = (const float4*)xr;
    float4 acc = make_float4(0.f, 0.f, 0.f, 0.f);
    int k = 0;
    for (; k + 4 <= deg; k += 4) {
        int2 p0 = g_pay[base + k];
        int2 p1 = g_pay[base + k + 1];
        int2 p2 = g_pay[base + k + 2];
        int2 p3 = g_pay[base + k + 3];
        float4 v0 = xr4[(size_t)p0.x * 32 + lane];
        float4 v1 = xr4[(size_t)p1.x * 32 + lane];
        float4 v2 = xr4[(size_t)p2.x * 32 + lane];
        float4 v3 = xr4[(size_t)p3.x * 32 + lane];
        float a0 = __int_as_float(p0.y), a1 = __int_as_float(p1.y);
        float a2 = __int_as_float(p2.y), a3 = __int_as_float(p3.y);
        acc.x += a0 * v0.x; acc.y += a0 * v0.y; acc.z += a0 * v0.z; acc.w += a0 * v0.w;
        acc.x += a1 * v1.x; acc.y += a1 * v1.y; acc.z += a1 * v1.z; acc.w += a1 * v1.w;
        acc.x += a2 * v2.x; acc.y += a2 * v2.y; acc.z += a2 * v2.z; acc.w += a2 * v2.w;
        acc.x += a3 * v3.x; acc.y += a3 * v3.y; acc.z += a3 * v3.z; acc.w += a3 * v3.w;
    }
    for (; k < deg; k++) {
        int2 p = g_pay[base + k];
        float a = __int_as_float(p.y);
        float4 v = xr4[(size_t)p.x * 32 + lane];
        acc.x += a * v.x; acc.y += a * v.y; acc.z += a * v.z; acc.w += a * v.w;
    }
    // out row = 256 floats = 64 float4: h-side cols [0,128), t-side [128,256)
    ((float4*)out)[(size_t)n * 64 + side * 32 + lane] = acc;
}

// ---------------- host ----------------
extern "C" void kernel_launch(void* const* d_in, const int* in_sizes, int n_in,
                              void* d_out, int out_size) {
    const float* x_e = (const float*)d_in[0];
    const float* x_r = (const float*)d_in[1];
    const float* Wh  = (const float*)d_in[2];
    const float* Wt  = (const float*)d_in[3];
    const float* Wr  = (const float*)d_in[4];
    const void*  ei  = d_in[5];
    const void*  rl  = d_in[6];
    float* out = (float*)d_out;

    int N_e = in_sizes[0] / D;
    int N_r = in_sizes[1] / D;
    int E   = in_sizes[6];
    int NH  = N_e * H;
    int NN  = 2 * N_e;
    int nb  = (NN + 1023) / 1024;
    int eb  = (E + 255) / 256;

    k_zero<<<(NH + 255) / 256, 256>>>(NH, NN);
    k_detect<<<1, 32>>>((const unsigned*)ei);

    long long pt = (long long)(N_e + N_r) * 32;
    k_proj<<<(int)((pt + 255) / 256), 256>>>(x_e, x_r, Wh, Wt, Wr, N_e, N_r);

    k_expsum<<<eb, 256>>>(ei, rl, E, N_e);
    k_recip<<<(NH + 255) / 256, 256>>>(NH);

    k_scan1<<<nb, 1024>>>(NN);
    k_scan2<<<1, 32>>>(nb);
    k_scan3<<<nb, 1024>>>(NN);

    k_fill<<<eb, 256>>>(ei, rl, E, N_e);

    long long gt = (long long)NN * 32;
    k_gather<<<(int)((gt + 511) / 512), 512>>>(x_r, out, N_e, NN);
}